// round 15
// baseline (speedup 1.0000x reference)
#include <cuda_runtime.h>
#include <cuda_bf16.h>
#include <cstdint>

// Problem constants
#define Bsz 64
#define Tt  512
#define Ee  512
#define Hh  512
#define G4  2048          // 4*H
#define NC  64            // CTAs per direction in recurrence
#define AROW 520          // SMEM row stride (bf16): conflict-free for ldmatrix
#define ZST 34            // z SMEM row stride (floats)
#define REC_THREADS 256
#define REC_SMEM (192*AROW*2 + 64*ZST*4)
#define WSTRIDE ((size_t)G4*1024)   // per-weight split-buffer stride (elems)

// ---------------- scratch (static device memory; no allocation) ----------------
__device__ float g_xz0[(size_t)Bsz*Tt*G4];
__device__ float g_xz1[(size_t)Bsz*Tt*G4];
__device__ __nv_bfloat16 g_hh[2*2*Bsz*Hh];
__device__ __nv_bfloat16 g_hl[2*2*Bsz*Hh];
__device__ int   g_cnt[4];                        // arrival counters (layer,dir)
__device__ int   g_flag[4];                       // release flags (layer,dir)
__device__ __nv_bfloat16 g_ahi [(size_t)Bsz*Tt*1024];
__device__ __nv_bfloat16 g_alo [(size_t)Bsz*Tt*1024];
__device__ __nv_bfloat16 g_whiT[2*WSTRIDE];
__device__ __nv_bfloat16 g_wloT[2*WSTRIDE];

__device__ __forceinline__ float sigm(float x) { return 1.0f / (1.0f + expf(-x)); }

__device__ __forceinline__ void cpasync16(uint32_t dst, const void* src) {
    asm volatile("cp.async.cg.shared.global [%0], [%1], 16;" :: "r"(dst), "l"(src));
}

#define LDSM4(r, addr)                                                         \
    asm volatile("ldmatrix.sync.aligned.m8n8.x4.shared.b16 {%0,%1,%2,%3}, [%4];" \
                 : "=r"((r)[0]), "=r"((r)[1]), "=r"((r)[2]), "=r"((r)[3])      \
                 : "r"(addr))

#define MMA16816(acc, a, b0, b1)                                               \
    asm volatile("mma.sync.aligned.m16n8k16.row.col.f32.bf16.bf16.f32 "        \
                 "{%0,%1,%2,%3}, {%4,%5,%6,%7}, {%8,%9}, {%0,%1,%2,%3};"       \
                 : "+f"((acc)[0]), "+f"((acc)[1]), "+f"((acc)[2]), "+f"((acc)[3]) \
                 : "r"((a)[0]), "r"((a)[1]), "r"((a)[2]), "r"((a)[3]),         \
                   "r"(b0), "r"(b1))

// ---------------- init ----------------
__global__ void k_init(int full) {
    int i = blockIdx.x * blockDim.x + threadIdx.x;
    uint4 z = make_uint4(0, 0, 0, 0);
    if (i < 16384) {
        ((uint4*)g_hh)[i] = z;
        ((uint4*)g_hl)[i] = z;
    }
    if (full && i < 4) { g_cnt[i] = 0; g_flag[i] = 0; }
}

// ---------------- fused embedding gather + bf16 hi/lo split ----------------
__global__ void k_gatherSplit(const int* __restrict__ ids, const float* __restrict__ emb,
                              __nv_bfloat16* __restrict__ hi, __nv_bfloat16* __restrict__ lo) {
    int i = blockIdx.x * blockDim.x + threadIdx.x;
    int bt = i >> 7;
    int c  = i & 127;
    int id = __ldg(&ids[bt]);
    float4 v = __ldg((const float4*)emb + (size_t)id * 128 + c);
    __nv_bfloat16 h0 = __float2bfloat16(v.x), h1 = __float2bfloat16(v.y);
    __nv_bfloat16 h2 = __float2bfloat16(v.z), h3 = __float2bfloat16(v.w);
    __nv_bfloat16 l0 = __float2bfloat16(v.x - __bfloat162float(h0));
    __nv_bfloat16 l1 = __float2bfloat16(v.y - __bfloat162float(h1));
    __nv_bfloat16 l2 = __float2bfloat16(v.z - __bfloat162float(h2));
    __nv_bfloat16 l3 = __float2bfloat16(v.w - __bfloat162float(h3));
    ((__nv_bfloat162*)hi)[i*2]   = __nv_bfloat162(h0, h1);
    ((__nv_bfloat162*)hi)[i*2+1] = __nv_bfloat162(h2, h3);
    ((__nv_bfloat162*)lo)[i*2]   = __nv_bfloat162(l0, l1);
    ((__nv_bfloat162*)lo)[i*2+1] = __nv_bfloat162(l2, l3);
}

// ---------------- W split + transpose, both directions in one launch ----------------
__global__ void __launch_bounds__(256)
k_splitW2(const float* __restrict__ W0, const float* __restrict__ W1,
          __nv_bfloat16* __restrict__ hiT, __nv_bfloat16* __restrict__ loT, int K) {
    __shared__ float t[32][33];
    const float* W = blockIdx.z ? W1 : W0;
    __nv_bfloat16* hi = hiT + (size_t)blockIdx.z * WSTRIDE;
    __nv_bfloat16* lo = loT + (size_t)blockIdx.z * WSTRIDE;
    const int kb = blockIdx.y * 32, nb = blockIdx.x * 32;
    const int tx = threadIdx.x, ty = threadIdx.y;
#pragma unroll
    for (int r = ty; r < 32; r += 8)
        t[r][tx] = W[(size_t)(kb + r) * G4 + nb + tx];
    __syncthreads();
#pragma unroll
    for (int r = ty; r < 32; r += 8) {
        float v = t[tx][r];
        __nv_bfloat16 h = __float2bfloat16(v);
        __nv_bfloat16 l = __float2bfloat16(v - __bfloat162float(h));
        size_t o = (size_t)(nb + r) * K + kb + tx;
        hi[o] = h;
        lo[o] = l;
    }
}

// ---------------- tensor-core projection GEMM (ldmatrix + 3-stage cp.async) ----------------
__global__ void __launch_bounds__(256)
k_hgemm(const __nv_bfloat16* __restrict__ Ahi, const __nv_bfloat16* __restrict__ Alo,
        const __nv_bfloat16* __restrict__ BhiT, const __nv_bfloat16* __restrict__ BloT,
        const float* __restrict__ bias, float* __restrict__ Y, int K) {
    const int N = 2048;
    __shared__ __nv_bfloat16 As[3][128 * 40];
    __shared__ __nv_bfloat16 Bs[3][128 * 40];

    const int tid = threadIdx.x;
    const int bm = blockIdx.y * 128, bn = blockIdx.x * 128;
    const int warp = tid >> 5, lane = tid & 31;
    const int mw = (warp & 1) * 64, nw = (warp >> 1) * 32;
    const int lr = lane >> 2, lc = (lane & 3) * 2;

    const int l_row = tid >> 2;
    const int l_q   = (tid & 3) * 8;

    float acc[4][4][4];
#pragma unroll
    for (int a = 0; a < 4; a++)
#pragma unroll
        for (int b = 0; b < 4; b++)
#pragma unroll
            for (int c = 0; c < 4; c++) acc[a][b][c] = 0.f;

    const int nk  = K >> 5;
    const int nch = 3 * nk;

    const uint32_t aoffc = (uint32_t)(((mw + (lane & 15)) * 40 + ((lane >> 4) << 3)) * 2);
    const uint32_t boffc = (uint32_t)(((nw + (lane & 7)) * 40 + ((lane >> 3) << 3)) * 2);
    const uint32_t sAb[3] = {(uint32_t)__cvta_generic_to_shared(As[0]),
                             (uint32_t)__cvta_generic_to_shared(As[1]),
                             (uint32_t)__cvta_generic_to_shared(As[2])};
    const uint32_t sBb[3] = {(uint32_t)__cvta_generic_to_shared(Bs[0]),
                             (uint32_t)__cvta_generic_to_shared(Bs[1]),
                             (uint32_t)__cvta_generic_to_shared(Bs[2])};
    const uint32_t ldst = (uint32_t)((l_row * 40 + l_q) * 2);
    const uint32_t ldst2 = ldst + (uint32_t)(64 * 40 * 2);

    auto issue = [&](int c) {
        const int seg = c / nk;
        const int k0 = (c - seg * nk) * 32;
        const __nv_bfloat16* Ap = (seg == 2) ? Alo  : Ahi;
        const __nv_bfloat16* Bp = (seg == 1) ? BloT : BhiT;
        const int st = c % 3;
        cpasync16(sAb[st] + ldst,  Ap + (size_t)(bm + l_row)      * K + k0 + l_q);
        cpasync16(sAb[st] + ldst2, Ap + (size_t)(bm + l_row + 64) * K + k0 + l_q);
        cpasync16(sBb[st] + ldst,  Bp + (size_t)(bn + l_row)      * K + k0 + l_q);
        cpasync16(sBb[st] + ldst2, Bp + (size_t)(bn + l_row + 64) * K + k0 + l_q);
        asm volatile("cp.async.commit_group;");
    };

    issue(0);
    issue(1);

    for (int c = 0; c < nch; ++c) {
        if (c + 1 < nch) asm volatile("cp.async.wait_group 1;" ::: "memory");
        else             asm volatile("cp.async.wait_group 0;" ::: "memory");
        __syncthreads();
        if (c + 2 < nch) issue(c + 2);

        const int st = c % 3;
        uint32_t bfr[4][4];
        {
            const uint32_t bb = sBb[st] + boffc;
#pragma unroll
            for (int nf = 0; nf < 4; nf++) LDSM4(bfr[nf], bb + (uint32_t)(nf * 8 * 40 * 2));
        }
#pragma unroll
        for (int half = 0; half < 2; ++half) {
            uint32_t af[4][4];
            const uint32_t ab = sAb[st] + aoffc + (uint32_t)(half * 32);
#pragma unroll
            for (int mf = 0; mf < 4; mf++) LDSM4(af[mf], ab + (uint32_t)(mf * 16 * 40 * 2));
#pragma unroll
            for (int mf = 0; mf < 4; mf++)
#pragma unroll
                for (int nf = 0; nf < 4; nf++)
                    MMA16816(acc[mf][nf], af[mf], bfr[nf][half * 2], bfr[nf][half * 2 + 1]);
        }
        __syncthreads();
    }

#pragma unroll
    for (int nf = 0; nf < 4; nf++) {
        const int col = bn + nw + nf * 8 + lc;
        const float bz0 = __ldg(&bias[col]), bz1 = __ldg(&bias[col + 1]);
#pragma unroll
        for (int mf = 0; mf < 4; mf++) {
            const int row0 = bm + mw + mf * 16 + lr;
            float2 v0, v1;
            v0.x = acc[mf][nf][0] + bz0; v0.y = acc[mf][nf][1] + bz1;
            v1.x = acc[mf][nf][2] + bz0; v1.y = acc[mf][nf][3] + bz1;
            *(float2*)&Y[(size_t)row0 * N + col]       = v0;
            *(float2*)&Y[(size_t)(row0 + 8) * N + col] = v1;
        }
    }
}

// ---------------- persistent bidirectional LSTM recurrence (R13 + flag barrier) ---------
__global__ void __launch_bounds__(REC_THREADS, 1)
k_rec(const float* __restrict__ xzf, const float* __restrict__ xzb,
      const float* __restrict__ Uf,  const float* __restrict__ Ub,
      float* __restrict__ hs_out, float* st_out,
      __nv_bfloat16* __restrict__ oh, __nv_bfloat16* __restrict__ ol, int layer) {
    extern __shared__ __nv_bfloat16 smb[];
    __nv_bfloat16* Ahi = smb;                  // [64][AROW]
    __nv_bfloat16* Alo = Ahi + 64 * AROW;
    __nv_bfloat16* Uhi = Alo + 64 * AROW;      // [32][AROW]
    __nv_bfloat16* Ulo = Uhi + 32 * AROW;
    float* zf = (float*)(Ulo + 32 * AROW);     // [64][ZST]

    const int dir = blockIdx.x >> 6;
    const int cid = blockIdx.x & 63;
    const float* xz = dir ? xzb : xzf;
    const float* U  = dir ? Ub  : Uf;
    int* cnt  = &g_cnt[layer * 2 + dir];
    int* flag = &g_flag[layer * 2 + dir];
    const int jbase = cid * 8;
    const int tid = threadIdx.x;
    const int lane = tid & 31, warp = tid >> 5;

    for (int idx = tid; idx < 512 * 32; idx += REC_THREADS) {
        int k = idx >> 5, n = idx & 31;
        float v = U[(size_t)k * G4 + (n >> 3) * Hh + jbase + (n & 7)];
        __nv_bfloat16 h = __float2bfloat16(v);
        Uhi[n * AROW + k] = h;
        Ulo[n * AROW + k] = __float2bfloat16(v - __bfloat162float(h));
    }

    const int eb = tid >> 2;
    const int eu = (tid & 3) * 2;
    float c0 = 0.f, c1 = 0.f;

    const int sr = tid >> 2, sq = tid & 3;

    const int mf  = warp & 3;
    const int nfg = warp >> 2;
    const int nb0 = nfg * 16;
    const uint32_t aoff  = (uint32_t)(((mf * 16 + (lane & 15)) * AROW + ((lane >> 4) << 3)) * 2);
    const uint32_t boff0 = (uint32_t)(((nb0 + (lane & 7)) * AROW + ((lane >> 3) << 3)) * 2);
    const uint32_t boff1 = boff0 + (uint32_t)(8 * AROW * 2);
    const uint32_t sAhi = (uint32_t)__cvta_generic_to_shared(Ahi);
    const uint32_t sAlo = (uint32_t)__cvta_generic_to_shared(Alo);
    const uint32_t sUhi = (uint32_t)__cvta_generic_to_shared(Uhi);
    const uint32_t sUlo = (uint32_t)__cvta_generic_to_shared(Ulo);

    const __nv_bfloat16* HHb = g_hh + (size_t)dir * 2 * Bsz * Hh;
    const __nv_bfloat16* HLb = g_hl + (size_t)dir * 2 * Bsz * Hh;

    __syncthreads();

    for (int s = 0; s < Tt; ++s) {
        const int tt = dir ? (Tt - 1 - s) : s;
        const int par = s & 1;
        const __nv_bfloat16* hpH = HHb + par * Bsz * Hh;
        const __nv_bfloat16* hpL = HLb + par * Bsz * Hh;
        __nv_bfloat16* hnH = (__nv_bfloat16*)HHb + (par ^ 1) * Bsz * Hh;
        __nv_bfloat16* hnL = (__nv_bfloat16*)HLb + (par ^ 1) * Bsz * Hh;

        // xz gate pre-activations first (DRAM latency overlaps staging)
        const float* xzp = xz + ((size_t)eb * Tt + tt) * G4 + jbase;
        float x[8];
#pragma unroll
        for (int g = 0; g < 4; ++g) {
            x[g * 2]     = __ldcs(xzp + g * 512 + eu);
            x[g * 2 + 1] = __ldcs(xzp + g * 512 + eu + 1);
        }

        // stage h hi (group 0), then h lo (group 1)
        {
            const uint4* srcH = (const uint4*)(hpH + sr * 512);
            const uint4* srcL = (const uint4*)(hpL + sr * 512);
            const uint32_t dH = sAhi + (uint32_t)(sr * AROW * 2) + sq * 16;
            const uint32_t dL = sAlo + (uint32_t)(sr * AROW * 2) + sq * 16;
#pragma unroll
            for (int i = 0; i < 16; ++i) cpasync16(dH + i * 64, srcH + sq + 4 * i);
            asm volatile("cp.async.commit_group;");
#pragma unroll
            for (int i = 0; i < 16; ++i) cpasync16(dL + i * 64, srcL + sq + 4 * i);
            asm volatile("cp.async.commit_group;");
        }

        float a0c0[4] = {0.f,0.f,0.f,0.f}, a0c1[4] = {0.f,0.f,0.f,0.f};
        float a1c0[4] = {0.f,0.f,0.f,0.f}, a1c1[4] = {0.f,0.f,0.f,0.f};

        asm volatile("cp.async.wait_group 1;" ::: "memory");
        __syncthreads();
#pragma unroll
        for (int p = 0; p < 2; ++p) {
            const uint32_t ab  = sAhi + aoff;
            const uint32_t bb0 = (p == 1 ? sUlo : sUhi) + boff0;
            const uint32_t bb1 = (p == 1 ? sUlo : sUhi) + boff1;
#pragma unroll 4
            for (int kb = 0; kb < 16; ++kb) {
                const uint32_t ko = kb * 64;
                uint32_t a0[4], a1[4], b0[4], b1[4];
                LDSM4(a0, ab + ko);
                LDSM4(a1, ab + ko + 32);
                LDSM4(b0, bb0 + ko);
                LDSM4(b1, bb1 + ko);
                MMA16816(a0c0, a0, b0[0], b0[1]);
                MMA16816(a0c1, a0, b1[0], b1[1]);
                MMA16816(a1c0, a1, b0[2], b0[3]);
                MMA16816(a1c1, a1, b1[2], b1[3]);
            }
        }
        asm volatile("cp.async.wait_group 0;" ::: "memory");
        __syncthreads();
        {
            const uint32_t ab  = sAlo + aoff;
            const uint32_t bb0 = sUhi + boff0;
            const uint32_t bb1 = sUhi + boff1;
#pragma unroll 4
            for (int kb = 0; kb < 16; ++kb) {
                const uint32_t ko = kb * 64;
                uint32_t a0[4], a1[4], b0[4], b1[4];
                LDSM4(a0, ab + ko);
                LDSM4(a1, ab + ko + 32);
                LDSM4(b0, bb0 + ko);
                LDSM4(b1, bb1 + ko);
                MMA16816(a0c0, a0, b0[0], b0[1]);
                MMA16816(a0c1, a0, b1[0], b1[1]);
                MMA16816(a1c0, a1, b0[2], b0[3]);
                MMA16816(a1c1, a1, b1[2], b1[3]);
            }
        }

        {
            const int lr = lane >> 2, lc = (lane & 3) * 2;
            const int zr = mf * 16 + lr;
            *(float2*)&zf[zr * ZST + nb0 + lc] =
                make_float2(a0c0[0] + a1c0[0], a0c0[1] + a1c0[1]);
            *(float2*)&zf[(zr + 8) * ZST + nb0 + lc] =
                make_float2(a0c0[2] + a1c0[2], a0c0[3] + a1c0[3]);
            *(float2*)&zf[zr * ZST + nb0 + 8 + lc] =
                make_float2(a0c1[0] + a1c1[0], a0c1[1] + a1c1[1]);
            *(float2*)&zf[(zr + 8) * ZST + nb0 + 8 + lc] =
                make_float2(a0c1[2] + a1c1[2], a0c1[3] + a1c1[3]);
        }
        __syncthreads();

        float hv[2];
        __nv_bfloat16 hb[2], lb[2];
#pragma unroll
        for (int e = 0; e < 2; ++e) {
            const int u = eu + e;
            const float zi = zf[eb * ZST + u]      + x[0 + e];
            const float zF = zf[eb * ZST + 8 + u]  + x[2 + e];
            const float zg = zf[eb * ZST + 16 + u] + x[4 + e];
            const float zo = zf[eb * ZST + 24 + u] + x[6 + e];
            const float ig = sigm(zi), fg = sigm(zF);
            const float gg = tanhf(zg), og = sigm(zo);
            float& c = e ? c1 : c0;
            c = fg * c + ig * gg;
            hv[e] = og * tanhf(c);
            hb[e] = __float2bfloat16(hv[e]);
            lb[e] = __float2bfloat16(hv[e] - __bfloat162float(hb[e]));
            hnH[eb * Hh + jbase + u] = hb[e];
            hnL[eb * Hh + jbase + u] = lb[e];
        }

        // fence + arrive; LAST arriver releases the flag (spinners poll flag only)
        __threadfence();
        __syncthreads();
        if (tid == 0) {
            int old = atomicAdd(cnt, 1);
            if (old == NC * (s + 1) - 1)
                asm volatile("st.release.gpu.global.s32 [%0], %1;"
                             :: "l"(flag), "r"(s + 1) : "memory");
        }

        // bulk output stores in the barrier shadow
        const size_t ob = ((size_t)eb * Tt + tt) * 1024 + dir * Hh + jbase + eu;
        if (hs_out != nullptr) {
            hs_out[ob]     = hv[0];
            hs_out[ob + 1] = hv[1];
            if (st_out != nullptr && s == Tt - 1) {
#pragma unroll
                for (int e = 0; e < 2; ++e) {
                    st_out[eb * 1024 + dir * Hh + jbase + eu + e] = hv[e];
                    st_out[Bsz * 1024 + eb * 1024 + dir * Hh + jbase + eu + e] = e ? c1 : c0;
                }
            }
        } else {
            oh[ob] = hb[0]; oh[ob + 1] = hb[1];
            ol[ob] = lb[0]; ol[ob + 1] = lb[1];
        }

        // spin on the once-written flag (broadcast read, no RMW interference)
        if (tid == 0) {
            int v;
            do {
                asm volatile("ld.acquire.gpu.global.s32 %0, [%1];"
                             : "=r"(v) : "l"(flag) : "memory");
            } while (v < s + 1);
        }
        __syncthreads();
    }
}

// ---------------- launch sequence ----------------
extern "C" void kernel_launch(void* const* d_in, const int* in_sizes, int n_in,
                              void* d_out, int out_size) {
    const int*   ids = (const int*)d_in[0];
    const float* emb = (const float*)d_in[1];
    const float *W1f = (const float*)d_in[2],  *U1f = (const float*)d_in[3],
                *b1f = (const float*)d_in[4];
    const float *W1b = (const float*)d_in[5],  *U1b = (const float*)d_in[6],
                *b1b = (const float*)d_in[7];
    const float *W2f = (const float*)d_in[8],  *U2f = (const float*)d_in[9],
                *b2f = (const float*)d_in[10];
    const float *W2b = (const float*)d_in[11], *U2b = (const float*)d_in[12],
                *b2b = (const float*)d_in[13];
    float* out = (float*)d_out;

    float *pxz0, *pxz1;
    __nv_bfloat16 *pahi, *palo, *pwhi, *pwlo;
    cudaGetSymbolAddress((void**)&pxz0, g_xz0);
    cudaGetSymbolAddress((void**)&pxz1, g_xz1);
    cudaGetSymbolAddress((void**)&pahi, g_ahi);
    cudaGetSymbolAddress((void**)&palo, g_alo);
    cudaGetSymbolAddress((void**)&pwhi, g_whiT);
    cudaGetSymbolAddress((void**)&pwlo, g_wloT);

    cudaFuncSetAttribute(k_rec, cudaFuncAttributeMaxDynamicSharedMemorySize, REC_SMEM);

    k_init<<<128, 256>>>(1);
    k_gatherSplit<<<16384, 256>>>(ids, emb, pahi, palo);

    const dim3 gg(G4 / 128, (Bsz * Tt) / 128);
    const dim3 tw(32, 8);

    // ----- layer 1 (K = 512) -----
    {
        const int K = Ee;
        k_splitW2<<<dim3(G4 / 32, K / 32, 2), tw>>>(W1f, W1b, pwhi, pwlo, K);
        k_hgemm<<<gg, 256>>>(pahi, palo, pwhi, pwlo, b1f, pxz0, K);
        k_hgemm<<<gg, 256>>>(pahi, palo, pwhi + WSTRIDE, pwlo + WSTRIDE, b1b, pxz1, K);
    }
    k_rec<<<2 * NC, REC_THREADS, REC_SMEM>>>(pxz0, pxz1, U1f, U1b,
                                             nullptr, nullptr, pahi, palo, 0);
    k_init<<<128, 256>>>(0);

    // ----- layer 2 (K = 1024) -----
    {
        const int K = 2 * Hh;
        k_splitW2<<<dim3(G4 / 32, K / 32, 2), tw>>>(W2f, W2b, pwhi, pwlo, K);
        k_hgemm<<<gg, 256>>>(pahi, palo, pwhi, pwlo, b2f, pxz0, K);
        k_hgemm<<<gg, 256>>>(pahi, palo, pwhi + WSTRIDE, pwlo + WSTRIDE, b2b, pxz1, K);
    }
    k_rec<<<2 * NC, REC_THREADS, REC_SMEM>>>(pxz0, pxz1, U2f, U2b, out,
                                             out + (size_t)Bsz * Tt * 1024,
                                             nullptr, nullptr, 1);
}

// round 16
// speedup vs baseline: 1.0804x; 1.0804x over previous
#include <cuda_runtime.h>
#include <cuda_bf16.h>
#include <cstdint>

// Problem constants
#define Bsz 64
#define Tt  512
#define Ee  512
#define Hh  512
#define G4  2048          // 4*H
#define NC  64            // CTAs per direction in recurrence
#define AROW 520          // SMEM row stride (bf16): conflict-free for ldmatrix
#define ZST 34            // z SMEM row stride (floats)
#define REC_THREADS 256
#define REC_SMEM (192*AROW*2 + 64*ZST*4)
#define WSTRIDE ((size_t)G4*1024)   // per-weight split-buffer stride (elems)

// ---------------- scratch (static device memory; no allocation) ----------------
__device__ float g_xz0[(size_t)Bsz*Tt*G4];
__device__ float g_xz1[(size_t)Bsz*Tt*G4];
__device__ __nv_bfloat16 g_hh[2*2*Bsz*Hh];
__device__ __nv_bfloat16 g_hl[2*2*Bsz*Hh];
__device__ int   g_cnt[4];
__device__ __nv_bfloat16 g_ahi [(size_t)Bsz*Tt*1024];
__device__ __nv_bfloat16 g_alo [(size_t)Bsz*Tt*1024];
__device__ __nv_bfloat16 g_whiT[2*WSTRIDE];
__device__ __nv_bfloat16 g_wloT[2*WSTRIDE];

__device__ __forceinline__ float sigm(float x) { return 1.0f / (1.0f + expf(-x)); }

__device__ __forceinline__ void cpasync16(uint32_t dst, const void* src) {
    asm volatile("cp.async.cg.shared.global [%0], [%1], 16;" :: "r"(dst), "l"(src));
}

#define LDSM4(r, addr)                                                         \
    asm volatile("ldmatrix.sync.aligned.m8n8.x4.shared.b16 {%0,%1,%2,%3}, [%4];" \
                 : "=r"((r)[0]), "=r"((r)[1]), "=r"((r)[2]), "=r"((r)[3])      \
                 : "r"(addr))

#define MMA16816(acc, a, b0, b1)                                               \
    asm volatile("mma.sync.aligned.m16n8k16.row.col.f32.bf16.bf16.f32 "        \
                 "{%0,%1,%2,%3}, {%4,%5,%6,%7}, {%8,%9}, {%0,%1,%2,%3};"       \
                 : "+f"((acc)[0]), "+f"((acc)[1]), "+f"((acc)[2]), "+f"((acc)[3]) \
                 : "r"((a)[0]), "r"((a)[1]), "r"((a)[2]), "r"((a)[3]),         \
                   "r"(b0), "r"(b1))

// ---------------- init ----------------
__global__ void k_init(int full) {
    int i = blockIdx.x * blockDim.x + threadIdx.x;
    uint4 z = make_uint4(0, 0, 0, 0);
    if (i < 16384) {
        ((uint4*)g_hh)[i] = z;
        ((uint4*)g_hl)[i] = z;
    }
    if (full && i < 4) g_cnt[i] = 0;
}

// ---------------- fused embedding gather + bf16 hi/lo split ----------------
__global__ void k_gatherSplit(const int* __restrict__ ids, const float* __restrict__ emb,
                              __nv_bfloat16* __restrict__ hi, __nv_bfloat16* __restrict__ lo) {
    int i = blockIdx.x * blockDim.x + threadIdx.x;
    int bt = i >> 7;
    int c  = i & 127;
    int id = __ldg(&ids[bt]);
    float4 v = __ldg((const float4*)emb + (size_t)id * 128 + c);
    __nv_bfloat16 h0 = __float2bfloat16(v.x), h1 = __float2bfloat16(v.y);
    __nv_bfloat16 h2 = __float2bfloat16(v.z), h3 = __float2bfloat16(v.w);
    __nv_bfloat16 l0 = __float2bfloat16(v.x - __bfloat162float(h0));
    __nv_bfloat16 l1 = __float2bfloat16(v.y - __bfloat162float(h1));
    __nv_bfloat16 l2 = __float2bfloat16(v.z - __bfloat162float(h2));
    __nv_bfloat16 l3 = __float2bfloat16(v.w - __bfloat162float(h3));
    ((__nv_bfloat162*)hi)[i*2]   = __nv_bfloat162(h0, h1);
    ((__nv_bfloat162*)hi)[i*2+1] = __nv_bfloat162(h2, h3);
    ((__nv_bfloat162*)lo)[i*2]   = __nv_bfloat162(l0, l1);
    ((__nv_bfloat162*)lo)[i*2+1] = __nv_bfloat162(l2, l3);
}

// ---------------- W split + transpose, both directions in one launch ----------------
__global__ void __launch_bounds__(256)
k_splitW2(const float* __restrict__ W0, const float* __restrict__ W1,
          __nv_bfloat16* __restrict__ hiT, __nv_bfloat16* __restrict__ loT, int K) {
    __shared__ float t[32][33];
    const float* W = blockIdx.z ? W1 : W0;
    __nv_bfloat16* hi = hiT + (size_t)blockIdx.z * WSTRIDE;
    __nv_bfloat16* lo = loT + (size_t)blockIdx.z * WSTRIDE;
    const int kb = blockIdx.y * 32, nb = blockIdx.x * 32;
    const int tx = threadIdx.x, ty = threadIdx.y;
#pragma unroll
    for (int r = ty; r < 32; r += 8)
        t[r][tx] = W[(size_t)(kb + r) * G4 + nb + tx];
    __syncthreads();
#pragma unroll
    for (int r = ty; r < 32; r += 8) {
        float v = t[tx][r];
        __nv_bfloat16 h = __float2bfloat16(v);
        __nv_bfloat16 l = __float2bfloat16(v - __bfloat162float(h));
        size_t o = (size_t)(nb + r) * K + kb + tx;
        hi[o] = h;
        lo[o] = l;
    }
}

// ---------------- tensor-core projection GEMM (ldmatrix + 4-stage cp.async, 1 sync) -----
__global__ void __launch_bounds__(256)
k_hgemm(const __nv_bfloat16* __restrict__ Ahi, const __nv_bfloat16* __restrict__ Alo,
        const __nv_bfloat16* __restrict__ BhiT, const __nv_bfloat16* __restrict__ BloT,
        const float* __restrict__ bias, float* __restrict__ Y, int K) {
    const int N = 2048;
    __shared__ __nv_bfloat16 As[4][128 * 40];
    __shared__ __nv_bfloat16 Bs[4][128 * 40];

    const int tid = threadIdx.x;
    const int bm = blockIdx.y * 128, bn = blockIdx.x * 128;
    const int warp = tid >> 5, lane = tid & 31;
    const int mw = (warp & 1) * 64, nw = (warp >> 1) * 32;
    const int lr = lane >> 2, lc = (lane & 3) * 2;

    const int l_row = tid >> 2;
    const int l_q   = (tid & 3) * 8;

    float acc[4][4][4];
#pragma unroll
    for (int a = 0; a < 4; a++)
#pragma unroll
        for (int b = 0; b < 4; b++)
#pragma unroll
            for (int c = 0; c < 4; c++) acc[a][b][c] = 0.f;

    const int nk  = K >> 5;
    const int nch = 3 * nk;

    const uint32_t aoffc = (uint32_t)(((mw + (lane & 15)) * 40 + ((lane >> 4) << 3)) * 2);
    const uint32_t boffc = (uint32_t)(((nw + (lane & 7)) * 40 + ((lane >> 3) << 3)) * 2);
    const uint32_t sAb[4] = {(uint32_t)__cvta_generic_to_shared(As[0]),
                             (uint32_t)__cvta_generic_to_shared(As[1]),
                             (uint32_t)__cvta_generic_to_shared(As[2]),
                             (uint32_t)__cvta_generic_to_shared(As[3])};
    const uint32_t sBb[4] = {(uint32_t)__cvta_generic_to_shared(Bs[0]),
                             (uint32_t)__cvta_generic_to_shared(Bs[1]),
                             (uint32_t)__cvta_generic_to_shared(Bs[2]),
                             (uint32_t)__cvta_generic_to_shared(Bs[3])};
    const uint32_t ldst = (uint32_t)((l_row * 40 + l_q) * 2);
    const uint32_t ldst2 = ldst + (uint32_t)(64 * 40 * 2);

    auto issue = [&](int c) {
        const int seg = c / nk;
        const int k0 = (c - seg * nk) * 32;
        const __nv_bfloat16* Ap = (seg == 2) ? Alo  : Ahi;
        const __nv_bfloat16* Bp = (seg == 1) ? BloT : BhiT;
        const int st = c & 3;
        cpasync16(sAb[st] + ldst,  Ap + (size_t)(bm + l_row)      * K + k0 + l_q);
        cpasync16(sAb[st] + ldst2, Ap + (size_t)(bm + l_row + 64) * K + k0 + l_q);
        cpasync16(sBb[st] + ldst,  Bp + (size_t)(bn + l_row)      * K + k0 + l_q);
        cpasync16(sBb[st] + ldst2, Bp + (size_t)(bn + l_row + 64) * K + k0 + l_q);
        asm volatile("cp.async.commit_group;");
    };

    issue(0);
    issue(1);
    issue(2);

    for (int c = 0; c < nch; ++c) {
        // wait until group c has landed (<= 2 groups still outstanding)
        if (c + 1 < nch) asm volatile("cp.async.wait_group 2;" ::: "memory");
        else             asm volatile("cp.async.wait_group 0;" ::: "memory");
        __syncthreads();          // single sync per chunk (4-stage: reuse is 2 syncs away)
        if (c + 3 < nch) issue(c + 3);

        const int st = c & 3;
        uint32_t bfr[4][4];
        {
            const uint32_t bb = sBb[st] + boffc;
#pragma unroll
            for (int nf = 0; nf < 4; nf++) LDSM4(bfr[nf], bb + (uint32_t)(nf * 8 * 40 * 2));
        }
#pragma unroll
        for (int half = 0; half < 2; ++half) {
            uint32_t af[4][4];
            const uint32_t ab = sAb[st] + aoffc + (uint32_t)(half * 32);
#pragma unroll
            for (int mf = 0; mf < 4; mf++) LDSM4(af[mf], ab + (uint32_t)(mf * 16 * 40 * 2));
#pragma unroll
            for (int mf = 0; mf < 4; mf++)
#pragma unroll
                for (int nf = 0; nf < 4; nf++)
                    MMA16816(acc[mf][nf], af[mf], bfr[nf][half * 2], bfr[nf][half * 2 + 1]);
        }
    }

#pragma unroll
    for (int nf = 0; nf < 4; nf++) {
        const int col = bn + nw + nf * 8 + lc;
        const float bz0 = __ldg(&bias[col]), bz1 = __ldg(&bias[col + 1]);
#pragma unroll
        for (int mf = 0; mf < 4; mf++) {
            const int row0 = bm + mw + mf * 16 + lr;
            float2 v0, v1;
            v0.x = acc[mf][nf][0] + bz0; v0.y = acc[mf][nf][1] + bz1;
            v1.x = acc[mf][nf][2] + bz0; v1.y = acc[mf][nf][3] + bz1;
            *(float2*)&Y[(size_t)row0 * N + col]       = v0;
            *(float2*)&Y[(size_t)(row0 + 8) * N + col] = v1;
        }
    }
}

// ---------------- persistent bidirectional LSTM recurrence (R13 + tid0 fence) -----------
__global__ void __launch_bounds__(REC_THREADS, 1)
k_rec(const float* __restrict__ xzf, const float* __restrict__ xzb,
      const float* __restrict__ Uf,  const float* __restrict__ Ub,
      float* __restrict__ hs_out, float* st_out,
      __nv_bfloat16* __restrict__ oh, __nv_bfloat16* __restrict__ ol, int layer) {
    extern __shared__ __nv_bfloat16 smb[];
    __nv_bfloat16* Ahi = smb;                  // [64][AROW]
    __nv_bfloat16* Alo = Ahi + 64 * AROW;
    __nv_bfloat16* Uhi = Alo + 64 * AROW;      // [32][AROW]
    __nv_bfloat16* Ulo = Uhi + 32 * AROW;
    float* zf = (float*)(Ulo + 32 * AROW);     // [64][ZST]

    const int dir = blockIdx.x >> 6;
    const int cid = blockIdx.x & 63;
    const float* xz = dir ? xzb : xzf;
    const float* U  = dir ? Ub  : Uf;
    int* cnt = &g_cnt[layer * 2 + dir];
    const int jbase = cid * 8;
    const int tid = threadIdx.x;
    const int lane = tid & 31, warp = tid >> 5;

    for (int idx = tid; idx < 512 * 32; idx += REC_THREADS) {
        int k = idx >> 5, n = idx & 31;
        float v = U[(size_t)k * G4 + (n >> 3) * Hh + jbase + (n & 7)];
        __nv_bfloat16 h = __float2bfloat16(v);
        Uhi[n * AROW + k] = h;
        Ulo[n * AROW + k] = __float2bfloat16(v - __bfloat162float(h));
    }

    const int eb = tid >> 2;
    const int eu = (tid & 3) * 2;
    float c0 = 0.f, c1 = 0.f;

    const int sr = tid >> 2, sq = tid & 3;

    const int mf  = warp & 3;
    const int nfg = warp >> 2;
    const int nb0 = nfg * 16;
    const uint32_t aoff  = (uint32_t)(((mf * 16 + (lane & 15)) * AROW + ((lane >> 4) << 3)) * 2);
    const uint32_t boff0 = (uint32_t)(((nb0 + (lane & 7)) * AROW + ((lane >> 3) << 3)) * 2);
    const uint32_t boff1 = boff0 + (uint32_t)(8 * AROW * 2);
    const uint32_t sAhi = (uint32_t)__cvta_generic_to_shared(Ahi);
    const uint32_t sAlo = (uint32_t)__cvta_generic_to_shared(Alo);
    const uint32_t sUhi = (uint32_t)__cvta_generic_to_shared(Uhi);
    const uint32_t sUlo = (uint32_t)__cvta_generic_to_shared(Ulo);

    const __nv_bfloat16* HHb = g_hh + (size_t)dir * 2 * Bsz * Hh;
    const __nv_bfloat16* HLb = g_hl + (size_t)dir * 2 * Bsz * Hh;

    __syncthreads();

    for (int s = 0; s < Tt; ++s) {
        const int tt = dir ? (Tt - 1 - s) : s;
        const int par = s & 1;
        const __nv_bfloat16* hpH = HHb + par * Bsz * Hh;
        const __nv_bfloat16* hpL = HLb + par * Bsz * Hh;
        __nv_bfloat16* hnH = (__nv_bfloat16*)HHb + (par ^ 1) * Bsz * Hh;
        __nv_bfloat16* hnL = (__nv_bfloat16*)HLb + (par ^ 1) * Bsz * Hh;

        // xz gate pre-activations first (DRAM latency overlaps staging)
        const float* xzp = xz + ((size_t)eb * Tt + tt) * G4 + jbase;
        float x[8];
#pragma unroll
        for (int g = 0; g < 4; ++g) {
            x[g * 2]     = __ldcs(xzp + g * 512 + eu);
            x[g * 2 + 1] = __ldcs(xzp + g * 512 + eu + 1);
        }

        // stage h hi (group 0), then h lo (group 1)
        {
            const uint4* srcH = (const uint4*)(hpH + sr * 512);
            const uint4* srcL = (const uint4*)(hpL + sr * 512);
            const uint32_t dH = sAhi + (uint32_t)(sr * AROW * 2) + sq * 16;
            const uint32_t dL = sAlo + (uint32_t)(sr * AROW * 2) + sq * 16;
#pragma unroll
            for (int i = 0; i < 16; ++i) cpasync16(dH + i * 64, srcH + sq + 4 * i);
            asm volatile("cp.async.commit_group;");
#pragma unroll
            for (int i = 0; i < 16; ++i) cpasync16(dL + i * 64, srcL + sq + 4 * i);
            asm volatile("cp.async.commit_group;");
        }

        float a0c0[4] = {0.f,0.f,0.f,0.f}, a0c1[4] = {0.f,0.f,0.f,0.f};
        float a1c0[4] = {0.f,0.f,0.f,0.f}, a1c1[4] = {0.f,0.f,0.f,0.f};

        asm volatile("cp.async.wait_group 1;" ::: "memory");
        __syncthreads();
#pragma unroll
        for (int p = 0; p < 2; ++p) {
            const uint32_t ab  = sAhi + aoff;
            const uint32_t bb0 = (p == 1 ? sUlo : sUhi) + boff0;
            const uint32_t bb1 = (p == 1 ? sUlo : sUhi) + boff1;
#pragma unroll 4
            for (int kb = 0; kb < 16; ++kb) {
                const uint32_t ko = kb * 64;
                uint32_t a0[4], a1[4], b0[4], b1[4];
                LDSM4(a0, ab + ko);
                LDSM4(a1, ab + ko + 32);
                LDSM4(b0, bb0 + ko);
                LDSM4(b1, bb1 + ko);
                MMA16816(a0c0, a0, b0[0], b0[1]);
                MMA16816(a0c1, a0, b1[0], b1[1]);
                MMA16816(a1c0, a1, b0[2], b0[3]);
                MMA16816(a1c1, a1, b1[2], b1[3]);
            }
        }
        asm volatile("cp.async.wait_group 0;" ::: "memory");
        __syncthreads();
        {
            const uint32_t ab  = sAlo + aoff;
            const uint32_t bb0 = sUhi + boff0;
            const uint32_t bb1 = sUhi + boff1;
#pragma unroll 4
            for (int kb = 0; kb < 16; ++kb) {
                const uint32_t ko = kb * 64;
                uint32_t a0[4], a1[4], b0[4], b1[4];
                LDSM4(a0, ab + ko);
                LDSM4(a1, ab + ko + 32);
                LDSM4(b0, bb0 + ko);
                LDSM4(b1, bb1 + ko);
                MMA16816(a0c0, a0, b0[0], b0[1]);
                MMA16816(a0c1, a0, b1[0], b1[1]);
                MMA16816(a1c0, a1, b0[2], b0[3]);
                MMA16816(a1c1, a1, b1[2], b1[3]);
            }
        }

        {
            const int lr = lane >> 2, lc = (lane & 3) * 2;
            const int zr = mf * 16 + lr;
            *(float2*)&zf[zr * ZST + nb0 + lc] =
                make_float2(a0c0[0] + a1c0[0], a0c0[1] + a1c0[1]);
            *(float2*)&zf[(zr + 8) * ZST + nb0 + lc] =
                make_float2(a0c0[2] + a1c0[2], a0c0[3] + a1c0[3]);
            *(float2*)&zf[zr * ZST + nb0 + 8 + lc] =
                make_float2(a0c1[0] + a1c1[0], a0c1[1] + a1c1[1]);
            *(float2*)&zf[(zr + 8) * ZST + nb0 + 8 + lc] =
                make_float2(a0c1[2] + a1c1[2], a0c1[3] + a1c1[3]);
        }
        __syncthreads();

        float hv[2];
        __nv_bfloat16 hb[2], lb[2];
#pragma unroll
        for (int e = 0; e < 2; ++e) {
            const int u = eu + e;
            const float zi = zf[eb * ZST + u]      + x[0 + e];
            const float zF = zf[eb * ZST + 8 + u]  + x[2 + e];
            const float zg = zf[eb * ZST + 16 + u] + x[4 + e];
            const float zo = zf[eb * ZST + 24 + u] + x[6 + e];
            const float ig = sigm(zi), fg = sigm(zF);
            const float gg = tanhf(zg), og = sigm(zo);
            float& c = e ? c1 : c0;
            c = fg * c + ig * gg;
            hv[e] = og * tanhf(c);
            hb[e] = __float2bfloat16(hv[e]);
            lb[e] = __float2bfloat16(hv[e] - __bfloat162float(hb[e]));
            hnH[eb * Hh + jbase + u] = hb[e];
            hnL[eb * Hh + jbase + u] = lb[e];
        }

        // block sync, then tid0-only gpu fence (cumulative) + arrive
        __syncthreads();
        if (tid == 0) {
            __threadfence();
            atomicAdd(cnt, 1);
        }

        // bulk output stores in the barrier shadow
        const size_t ob = ((size_t)eb * Tt + tt) * 1024 + dir * Hh + jbase + eu;
        if (hs_out != nullptr) {
            hs_out[ob]     = hv[0];
            hs_out[ob + 1] = hv[1];
            if (st_out != nullptr && s == Tt - 1) {
#pragma unroll
                for (int e = 0; e < 2; ++e) {
                    st_out[eb * 1024 + dir * Hh + jbase + eu + e] = hv[e];
                    st_out[Bsz * 1024 + eb * 1024 + dir * Hh + jbase + eu + e] = e ? c1 : c0;
                }
            }
        } else {
            oh[ob] = hb[0]; oh[ob + 1] = hb[1];
            ol[ob] = lb[0]; ol[ob + 1] = lb[1];
        }

        if (tid == 0) {
            const int target = NC * (s + 1);
            int v;
            do {
                asm volatile("ld.acquire.gpu.global.s32 %0, [%1];"
                             : "=r"(v) : "l"(cnt) : "memory");
            } while (v < target);
        }
        __syncthreads();
    }
}

// ---------------- launch sequence ----------------
extern "C" void kernel_launch(void* const* d_in, const int* in_sizes, int n_in,
                              void* d_out, int out_size) {
    const int*   ids = (const int*)d_in[0];
    const float* emb = (const float*)d_in[1];
    const float *W1f = (const float*)d_in[2],  *U1f = (const float*)d_in[3],
                *b1f = (const float*)d_in[4];
    const float *W1b = (const float*)d_in[5],  *U1b = (const float*)d_in[6],
                *b1b = (const float*)d_in[7];
    const float *W2f = (const float*)d_in[8],  *U2f = (const float*)d_in[9],
                *b2f = (const float*)d_in[10];
    const float *W2b = (const float*)d_in[11], *U2b = (const float*)d_in[12],
                *b2b = (const float*)d_in[13];
    float* out = (float*)d_out;

    float *pxz0, *pxz1;
    __nv_bfloat16 *pahi, *palo, *pwhi, *pwlo;
    cudaGetSymbolAddress((void**)&pxz0, g_xz0);
    cudaGetSymbolAddress((void**)&pxz1, g_xz1);
    cudaGetSymbolAddress((void**)&pahi, g_ahi);
    cudaGetSymbolAddress((void**)&palo, g_alo);
    cudaGetSymbolAddress((void**)&pwhi, g_whiT);
    cudaGetSymbolAddress((void**)&pwlo, g_wloT);

    cudaFuncSetAttribute(k_rec, cudaFuncAttributeMaxDynamicSharedMemorySize, REC_SMEM);

    k_init<<<128, 256>>>(1);
    k_gatherSplit<<<16384, 256>>>(ids, emb, pahi, palo);

    const dim3 gg(G4 / 128, (Bsz * Tt) / 128);
    const dim3 tw(32, 8);

    // ----- layer 1 (K = 512) -----
    {
        const int K = Ee;
        k_splitW2<<<dim3(G4 / 32, K / 32, 2), tw>>>(W1f, W1b, pwhi, pwlo, K);
        k_hgemm<<<gg, 256>>>(pahi, palo, pwhi, pwlo, b1f, pxz0, K);
        k_hgemm<<<gg, 256>>>(pahi, palo, pwhi + WSTRIDE, pwlo + WSTRIDE, b1b, pxz1, K);
    }
    k_rec<<<2 * NC, REC_THREADS, REC_SMEM>>>(pxz0, pxz1, U1f, U1b,
                                             nullptr, nullptr, pahi, palo, 0);
    k_init<<<128, 256>>>(0);

    // ----- layer 2 (K = 1024) -----
    {
        const int K = 2 * Hh;
        k_splitW2<<<dim3(G4 / 32, K / 32, 2), tw>>>(W2f, W2b, pwhi, pwlo, K);
        k_hgemm<<<gg, 256>>>(pahi, palo, pwhi, pwlo, b2f, pxz0, K);
        k_hgemm<<<gg, 256>>>(pahi, palo, pwhi + WSTRIDE, pwlo + WSTRIDE, b2b, pxz1, K);
    }
    k_rec<<<2 * NC, REC_THREADS, REC_SMEM>>>(pxz0, pxz1, U2f, U2b, out,
                                             out + (size_t)Bsz * Tt * 1024,
                                             nullptr, nullptr, 1);
}

// round 17
// speedup vs baseline: 1.1677x; 1.0808x over previous
#include <cuda_runtime.h>
#include <cuda_bf16.h>
#include <cstdint>

// Problem constants
#define Bsz 64
#define Tt  512
#define Ee  512
#define Hh  512
#define G4  2048          // 4*H
#define NC  64            // CTAs per direction in recurrence
#define AROW 520          // SMEM row stride (bf16): conflict-free for ldmatrix
#define ZST 34            // z SMEM row stride (floats)
#define REC_THREADS 256
#define REC_SMEM (192*AROW*2 + 64*ZST*4)
#define WSTRIDE ((size_t)G4*1024)   // per-weight split-buffer stride (elems)

// ---------------- scratch (static device memory; no allocation) ----------------
__device__ float g_xz0[(size_t)Bsz*Tt*G4];
__device__ float g_xz1[(size_t)Bsz*Tt*G4];
__device__ __nv_bfloat16 g_hh[2*2*Bsz*Hh];
__device__ __nv_bfloat16 g_hl[2*2*Bsz*Hh];
__device__ int   g_cnt[4];
__device__ __nv_bfloat16 g_ahi [(size_t)Bsz*Tt*1024];
__device__ __nv_bfloat16 g_alo [(size_t)Bsz*Tt*1024];
__device__ __nv_bfloat16 g_whiT[2*WSTRIDE];
__device__ __nv_bfloat16 g_wloT[2*WSTRIDE];

__device__ __forceinline__ float sigm(float x) { return 1.0f / (1.0f + expf(-x)); }

__device__ __forceinline__ void cpasync16(uint32_t dst, const void* src) {
    asm volatile("cp.async.cg.shared.global [%0], [%1], 16;" :: "r"(dst), "l"(src));
}

#define LDSM4(r, addr)                                                         \
    asm volatile("ldmatrix.sync.aligned.m8n8.x4.shared.b16 {%0,%1,%2,%3}, [%4];" \
                 : "=r"((r)[0]), "=r"((r)[1]), "=r"((r)[2]), "=r"((r)[3])      \
                 : "r"(addr))

#define MMA16816(acc, a, b0, b1)                                               \
    asm volatile("mma.sync.aligned.m16n8k16.row.col.f32.bf16.bf16.f32 "        \
                 "{%0,%1,%2,%3}, {%4,%5,%6,%7}, {%8,%9}, {%0,%1,%2,%3};"       \
                 : "+f"((acc)[0]), "+f"((acc)[1]), "+f"((acc)[2]), "+f"((acc)[3]) \
                 : "r"((a)[0]), "r"((a)[1]), "r"((a)[2]), "r"((a)[3]),         \
                   "r"(b0), "r"(b1))

// ---------------- init ----------------
__global__ void k_init(int full) {
    int i = blockIdx.x * blockDim.x + threadIdx.x;
    uint4 z = make_uint4(0, 0, 0, 0);
    if (i < 16384) {
        ((uint4*)g_hh)[i] = z;
        ((uint4*)g_hl)[i] = z;
    }
    if (full && i < 4) g_cnt[i] = 0;
}

// ---------------- fused embedding gather + bf16 hi/lo split ----------------
__global__ void k_gatherSplit(const int* __restrict__ ids, const float* __restrict__ emb,
                              __nv_bfloat16* __restrict__ hi, __nv_bfloat16* __restrict__ lo) {
    int i = blockIdx.x * blockDim.x + threadIdx.x;
    int bt = i >> 7;
    int c  = i & 127;
    int id = __ldg(&ids[bt]);
    float4 v = __ldg((const float4*)emb + (size_t)id * 128 + c);
    __nv_bfloat16 h0 = __float2bfloat16(v.x), h1 = __float2bfloat16(v.y);
    __nv_bfloat16 h2 = __float2bfloat16(v.z), h3 = __float2bfloat16(v.w);
    __nv_bfloat16 l0 = __float2bfloat16(v.x - __bfloat162float(h0));
    __nv_bfloat16 l1 = __float2bfloat16(v.y - __bfloat162float(h1));
    __nv_bfloat16 l2 = __float2bfloat16(v.z - __bfloat162float(h2));
    __nv_bfloat16 l3 = __float2bfloat16(v.w - __bfloat162float(h3));
    ((__nv_bfloat162*)hi)[i*2]   = __nv_bfloat162(h0, h1);
    ((__nv_bfloat162*)hi)[i*2+1] = __nv_bfloat162(h2, h3);
    ((__nv_bfloat162*)lo)[i*2]   = __nv_bfloat162(l0, l1);
    ((__nv_bfloat162*)lo)[i*2+1] = __nv_bfloat162(l2, l3);
}

// ---------------- W split + transpose, both directions in one launch ----------------
__global__ void __launch_bounds__(256)
k_splitW2(const float* __restrict__ W0, const float* __restrict__ W1,
          __nv_bfloat16* __restrict__ hiT, __nv_bfloat16* __restrict__ loT, int K) {
    __shared__ float t[32][33];
    const float* W = blockIdx.z ? W1 : W0;
    __nv_bfloat16* hi = hiT + (size_t)blockIdx.z * WSTRIDE;
    __nv_bfloat16* lo = loT + (size_t)blockIdx.z * WSTRIDE;
    const int kb = blockIdx.y * 32, nb = blockIdx.x * 32;
    const int tx = threadIdx.x, ty = threadIdx.y;
#pragma unroll
    for (int r = ty; r < 32; r += 8)
        t[r][tx] = W[(size_t)(kb + r) * G4 + nb + tx];
    __syncthreads();
#pragma unroll
    for (int r = ty; r < 32; r += 8) {
        float v = t[tx][r];
        __nv_bfloat16 h = __float2bfloat16(v);
        __nv_bfloat16 l = __float2bfloat16(v - __bfloat162float(h));
        size_t o = (size_t)(nb + r) * K + kb + tx;
        hi[o] = h;
        lo[o] = l;
    }
}

// ---------------- tensor-core projection GEMM (R13: ldmatrix + 3-stage cp.async) --------
__global__ void __launch_bounds__(256)
k_hgemm(const __nv_bfloat16* __restrict__ Ahi, const __nv_bfloat16* __restrict__ Alo,
        const __nv_bfloat16* __restrict__ BhiT, const __nv_bfloat16* __restrict__ BloT,
        const float* __restrict__ bias, float* __restrict__ Y, int K) {
    const int N = 2048;
    __shared__ __nv_bfloat16 As[3][128 * 40];
    __shared__ __nv_bfloat16 Bs[3][128 * 40];

    const int tid = threadIdx.x;
    const int bm = blockIdx.y * 128, bn = blockIdx.x * 128;
    const int warp = tid >> 5, lane = tid & 31;
    const int mw = (warp & 1) * 64, nw = (warp >> 1) * 32;
    const int lr = lane >> 2, lc = (lane & 3) * 2;

    const int l_row = tid >> 2;
    const int l_q   = (tid & 3) * 8;

    float acc[4][4][4];
#pragma unroll
    for (int a = 0; a < 4; a++)
#pragma unroll
        for (int b = 0; b < 4; b++)
#pragma unroll
            for (int c = 0; c < 4; c++) acc[a][b][c] = 0.f;

    const int nk  = K >> 5;
    const int nch = 3 * nk;

    const uint32_t aoffc = (uint32_t)(((mw + (lane & 15)) * 40 + ((lane >> 4) << 3)) * 2);
    const uint32_t boffc = (uint32_t)(((nw + (lane & 7)) * 40 + ((lane >> 3) << 3)) * 2);
    const uint32_t sAb[3] = {(uint32_t)__cvta_generic_to_shared(As[0]),
                             (uint32_t)__cvta_generic_to_shared(As[1]),
                             (uint32_t)__cvta_generic_to_shared(As[2])};
    const uint32_t sBb[3] = {(uint32_t)__cvta_generic_to_shared(Bs[0]),
                             (uint32_t)__cvta_generic_to_shared(Bs[1]),
                             (uint32_t)__cvta_generic_to_shared(Bs[2])};
    const uint32_t ldst = (uint32_t)((l_row * 40 + l_q) * 2);
    const uint32_t ldst2 = ldst + (uint32_t)(64 * 40 * 2);

    auto issue = [&](int c) {
        const int seg = c / nk;
        const int k0 = (c - seg * nk) * 32;
        const __nv_bfloat16* Ap = (seg == 2) ? Alo  : Ahi;
        const __nv_bfloat16* Bp = (seg == 1) ? BloT : BhiT;
        const int st = c % 3;
        cpasync16(sAb[st] + ldst,  Ap + (size_t)(bm + l_row)      * K + k0 + l_q);
        cpasync16(sAb[st] + ldst2, Ap + (size_t)(bm + l_row + 64) * K + k0 + l_q);
        cpasync16(sBb[st] + ldst,  Bp + (size_t)(bn + l_row)      * K + k0 + l_q);
        cpasync16(sBb[st] + ldst2, Bp + (size_t)(bn + l_row + 64) * K + k0 + l_q);
        asm volatile("cp.async.commit_group;");
    };

    issue(0);
    issue(1);

    for (int c = 0; c < nch; ++c) {
        if (c + 1 < nch) asm volatile("cp.async.wait_group 1;" ::: "memory");
        else             asm volatile("cp.async.wait_group 0;" ::: "memory");
        __syncthreads();
        if (c + 2 < nch) issue(c + 2);

        const int st = c % 3;
        uint32_t bfr[4][4];
        {
            const uint32_t bb = sBb[st] + boffc;
#pragma unroll
            for (int nf = 0; nf < 4; nf++) LDSM4(bfr[nf], bb + (uint32_t)(nf * 8 * 40 * 2));
        }
#pragma unroll
        for (int half = 0; half < 2; ++half) {
            uint32_t af[4][4];
            const uint32_t ab = sAb[st] + aoffc + (uint32_t)(half * 32);
#pragma unroll
            for (int mf = 0; mf < 4; mf++) LDSM4(af[mf], ab + (uint32_t)(mf * 16 * 40 * 2));
#pragma unroll
            for (int mf = 0; mf < 4; mf++)
#pragma unroll
                for (int nf = 0; nf < 4; nf++)
                    MMA16816(acc[mf][nf], af[mf], bfr[nf][half * 2], bfr[nf][half * 2 + 1]);
        }
        __syncthreads();
    }

#pragma unroll
    for (int nf = 0; nf < 4; nf++) {
        const int col = bn + nw + nf * 8 + lc;
        const float bz0 = __ldg(&bias[col]), bz1 = __ldg(&bias[col + 1]);
#pragma unroll
        for (int mf = 0; mf < 4; mf++) {
            const int row0 = bm + mw + mf * 16 + lr;
            float2 v0, v1;
            v0.x = acc[mf][nf][0] + bz0; v0.y = acc[mf][nf][1] + bz1;
            v1.x = acc[mf][nf][2] + bz0; v1.y = acc[mf][nf][3] + bz1;
            *(float2*)&Y[(size_t)row0 * N + col]       = v0;
            *(float2*)&Y[(size_t)(row0 + 8) * N + col] = v1;
        }
    }
}

// ---------------- persistent bidirectional LSTM recurrence (fused 3-product mma) --------
// Per kb: 8 LDSM.x4 (Ahi,Alo,Uhi,Ulo) feed 12 MMAs — 33% less SMEM wavefront
// traffic than the 3-pass loop. Single wait_group 0 before compute.
__global__ void __launch_bounds__(REC_THREADS, 1)
k_rec(const float* __restrict__ xzf, const float* __restrict__ xzb,
      const float* __restrict__ Uf,  const float* __restrict__ Ub,
      float* __restrict__ hs_out, float* st_out,
      __nv_bfloat16* __restrict__ oh, __nv_bfloat16* __restrict__ ol, int layer) {
    extern __shared__ __nv_bfloat16 smb[];
    __nv_bfloat16* Ahi = smb;                  // [64][AROW]
    __nv_bfloat16* Alo = Ahi + 64 * AROW;
    __nv_bfloat16* Uhi = Alo + 64 * AROW;      // [32][AROW]
    __nv_bfloat16* Ulo = Uhi + 32 * AROW;
    float* zf = (float*)(Ulo + 32 * AROW);     // [64][ZST]

    const int dir = blockIdx.x >> 6;
    const int cid = blockIdx.x & 63;
    const float* xz = dir ? xzb : xzf;
    const float* U  = dir ? Ub  : Uf;
    int* cnt = &g_cnt[layer * 2 + dir];
    const int jbase = cid * 8;
    const int tid = threadIdx.x;
    const int lane = tid & 31, warp = tid >> 5;

    for (int idx = tid; idx < 512 * 32; idx += REC_THREADS) {
        int k = idx >> 5, n = idx & 31;
        float v = U[(size_t)k * G4 + (n >> 3) * Hh + jbase + (n & 7)];
        __nv_bfloat16 h = __float2bfloat16(v);
        Uhi[n * AROW + k] = h;
        Ulo[n * AROW + k] = __float2bfloat16(v - __bfloat162float(h));
    }

    const int eb = tid >> 2;
    const int eu = (tid & 3) * 2;
    float c0 = 0.f, c1 = 0.f;

    const int sr = tid >> 2, sq = tid & 3;

    const int mf  = warp & 3;
    const int nfg = warp >> 2;
    const int nb0 = nfg * 16;
    const uint32_t aoff  = (uint32_t)(((mf * 16 + (lane & 15)) * AROW + ((lane >> 4) << 3)) * 2);
    const uint32_t boff0 = (uint32_t)(((nb0 + (lane & 7)) * AROW + ((lane >> 3) << 3)) * 2);
    const uint32_t boff1 = boff0 + (uint32_t)(8 * AROW * 2);
    const uint32_t sAhi = (uint32_t)__cvta_generic_to_shared(Ahi);
    const uint32_t sAlo = (uint32_t)__cvta_generic_to_shared(Alo);
    const uint32_t sUhi = (uint32_t)__cvta_generic_to_shared(Uhi);
    const uint32_t sUlo = (uint32_t)__cvta_generic_to_shared(Ulo);

    const __nv_bfloat16* HHb = g_hh + (size_t)dir * 2 * Bsz * Hh;
    const __nv_bfloat16* HLb = g_hl + (size_t)dir * 2 * Bsz * Hh;

    __syncthreads();

    for (int s = 0; s < Tt; ++s) {
        const int tt = dir ? (Tt - 1 - s) : s;
        const int par = s & 1;
        const __nv_bfloat16* hpH = HHb + par * Bsz * Hh;
        const __nv_bfloat16* hpL = HLb + par * Bsz * Hh;
        __nv_bfloat16* hnH = (__nv_bfloat16*)HHb + (par ^ 1) * Bsz * Hh;
        __nv_bfloat16* hnL = (__nv_bfloat16*)HLb + (par ^ 1) * Bsz * Hh;

        // xz gate pre-activations first (DRAM latency overlaps staging)
        const float* xzp = xz + ((size_t)eb * Tt + tt) * G4 + jbase;
        float x[8];
#pragma unroll
        for (int g = 0; g < 4; ++g) {
            x[g * 2]     = __ldcs(xzp + g * 512 + eu);
            x[g * 2 + 1] = __ldcs(xzp + g * 512 + eu + 1);
        }

        // stage h hi + lo (single logical group; one wait)
        {
            const uint4* srcH = (const uint4*)(hpH + sr * 512);
            const uint4* srcL = (const uint4*)(hpL + sr * 512);
            const uint32_t dH = sAhi + (uint32_t)(sr * AROW * 2) + sq * 16;
            const uint32_t dL = sAlo + (uint32_t)(sr * AROW * 2) + sq * 16;
#pragma unroll
            for (int i = 0; i < 16; ++i) cpasync16(dH + i * 64, srcH + sq + 4 * i);
#pragma unroll
            for (int i = 0; i < 16; ++i) cpasync16(dL + i * 64, srcL + sq + 4 * i);
            asm volatile("cp.async.commit_group;");
        }

        float a0c0[4] = {0.f,0.f,0.f,0.f}, a0c1[4] = {0.f,0.f,0.f,0.f};
        float a1c0[4] = {0.f,0.f,0.f,0.f}, a1c1[4] = {0.f,0.f,0.f,0.f};

        asm volatile("cp.async.wait_group 0;" ::: "memory");
        __syncthreads();

        // fused 3-product loop: per kb, 8 LDSM feed 12 MMAs
        {
            const uint32_t abh = sAhi + aoff, abl = sAlo + aoff;
            const uint32_t bbh0 = sUhi + boff0, bbh1 = sUhi + boff1;
            const uint32_t bbl0 = sUlo + boff0, bbl1 = sUlo + boff1;
#pragma unroll 4
            for (int kb = 0; kb < 16; ++kb) {
                const uint32_t ko = kb * 64;
                uint32_t a0h[4], a1h[4], a0l[4], a1l[4];
                uint32_t bh0[4], bh1[4], bl0[4], bl1[4];
                LDSM4(a0h, abh + ko);
                LDSM4(a1h, abh + ko + 32);
                LDSM4(bh0, bbh0 + ko);
                LDSM4(bh1, bbh1 + ko);
                LDSM4(a0l, abl + ko);
                LDSM4(a1l, abl + ko + 32);
                LDSM4(bl0, bbl0 + ko);
                LDSM4(bl1, bbl1 + ko);
                // Ahi @ Uhi
                MMA16816(a0c0, a0h, bh0[0], bh0[1]);
                MMA16816(a0c1, a0h, bh1[0], bh1[1]);
                MMA16816(a1c0, a1h, bh0[2], bh0[3]);
                MMA16816(a1c1, a1h, bh1[2], bh1[3]);
                // Ahi @ Ulo
                MMA16816(a0c0, a0h, bl0[0], bl0[1]);
                MMA16816(a0c1, a0h, bl1[0], bl1[1]);
                MMA16816(a1c0, a1h, bl0[2], bl0[3]);
                MMA16816(a1c1, a1h, bl1[2], bl1[3]);
                // Alo @ Uhi
                MMA16816(a0c0, a0l, bh0[0], bh0[1]);
                MMA16816(a0c1, a0l, bh1[0], bh1[1]);
                MMA16816(a1c0, a1l, bh0[2], bh0[3]);
                MMA16816(a1c1, a1l, bh1[2], bh1[3]);
            }
        }

        {
            const int lr = lane >> 2, lc = (lane & 3) * 2;
            const int zr = mf * 16 + lr;
            *(float2*)&zf[zr * ZST + nb0 + lc] =
                make_float2(a0c0[0] + a1c0[0], a0c0[1] + a1c0[1]);
            *(float2*)&zf[(zr + 8) * ZST + nb0 + lc] =
                make_float2(a0c0[2] + a1c0[2], a0c0[3] + a1c0[3]);
            *(float2*)&zf[zr * ZST + nb0 + 8 + lc] =
                make_float2(a0c1[0] + a1c1[0], a0c1[1] + a1c1[1]);
            *(float2*)&zf[(zr + 8) * ZST + nb0 + 8 + lc] =
                make_float2(a0c1[2] + a1c1[2], a0c1[3] + a1c1[3]);
        }
        __syncthreads();

        float hv[2];
        __nv_bfloat16 hb[2], lb[2];
#pragma unroll
        for (int e = 0; e < 2; ++e) {
            const int u = eu + e;
            const float zi = zf[eb * ZST + u]      + x[0 + e];
            const float zF = zf[eb * ZST + 8 + u]  + x[2 + e];
            const float zg = zf[eb * ZST + 16 + u] + x[4 + e];
            const float zo = zf[eb * ZST + 24 + u] + x[6 + e];
            const float ig = sigm(zi), fg = sigm(zF);
            const float gg = tanhf(zg), og = sigm(zo);
            float& c = e ? c1 : c0;
            c = fg * c + ig * gg;
            hv[e] = og * tanhf(c);
            hb[e] = __float2bfloat16(hv[e]);
            lb[e] = __float2bfloat16(hv[e] - __bfloat162float(hb[e]));
            hnH[eb * Hh + jbase + u] = hb[e];
            hnL[eb * Hh + jbase + u] = lb[e];
        }

        // block sync, then tid0-only gpu fence (cumulative) + arrive
        __syncthreads();
        if (tid == 0) {
            __threadfence();
            atomicAdd(cnt, 1);
        }

        // bulk output stores in the barrier shadow
        const size_t ob = ((size_t)eb * Tt + tt) * 1024 + dir * Hh + jbase + eu;
        if (hs_out != nullptr) {
            hs_out[ob]     = hv[0];
            hs_out[ob + 1] = hv[1];
            if (st_out != nullptr && s == Tt - 1) {
#pragma unroll
                for (int e = 0; e < 2; ++e) {
                    st_out[eb * 1024 + dir * Hh + jbase + eu + e] = hv[e];
                    st_out[Bsz * 1024 + eb * 1024 + dir * Hh + jbase + eu + e] = e ? c1 : c0;
                }
            }
        } else {
            oh[ob] = hb[0]; oh[ob + 1] = hb[1];
            ol[ob] = lb[0]; ol[ob + 1] = lb[1];
        }

        if (tid == 0) {
            const int target = NC * (s + 1);
            int v;
            do {
                asm volatile("ld.acquire.gpu.global.s32 %0, [%1];"
                             : "=r"(v) : "l"(cnt) : "memory");
            } while (v < target);
        }
        __syncthreads();
    }
}

// ---------------- launch sequence ----------------
extern "C" void kernel_launch(void* const* d_in, const int* in_sizes, int n_in,
                              void* d_out, int out_size) {
    const int*   ids = (const int*)d_in[0];
    const float* emb = (const float*)d_in[1];
    const float *W1f = (const float*)d_in[2],  *U1f = (const float*)d_in[3],
                *b1f = (const float*)d_in[4];
    const float *W1b = (const float*)d_in[5],  *U1b = (const float*)d_in[6],
                *b1b = (const float*)d_in[7];
    const float *W2f = (const float*)d_in[8],  *U2f = (const float*)d_in[9],
                *b2f = (const float*)d_in[10];
    const float *W2b = (const float*)d_in[11], *U2b = (const float*)d_in[12],
                *b2b = (const float*)d_in[13];
    float* out = (float*)d_out;

    float *pxz0, *pxz1;
    __nv_bfloat16 *pahi, *palo, *pwhi, *pwlo;
    cudaGetSymbolAddress((void**)&pxz0, g_xz0);
    cudaGetSymbolAddress((void**)&pxz1, g_xz1);
    cudaGetSymbolAddress((void**)&pahi, g_ahi);
    cudaGetSymbolAddress((void**)&palo, g_alo);
    cudaGetSymbolAddress((void**)&pwhi, g_whiT);
    cudaGetSymbolAddress((void**)&pwlo, g_wloT);

    cudaFuncSetAttribute(k_rec, cudaFuncAttributeMaxDynamicSharedMemorySize, REC_SMEM);

    k_init<<<128, 256>>>(1);
    k_gatherSplit<<<16384, 256>>>(ids, emb, pahi, palo);

    const dim3 gg(G4 / 128, (Bsz * Tt) / 128);
    const dim3 tw(32, 8);

    // ----- layer 1 (K = 512) -----
    {
        const int K = Ee;
        k_splitW2<<<dim3(G4 / 32, K / 32, 2), tw>>>(W1f, W1b, pwhi, pwlo, K);
        k_hgemm<<<gg, 256>>>(pahi, palo, pwhi, pwlo, b1f, pxz0, K);
        k_hgemm<<<gg, 256>>>(pahi, palo, pwhi + WSTRIDE, pwlo + WSTRIDE, b1b, pxz1, K);
    }
    k_rec<<<2 * NC, REC_THREADS, REC_SMEM>>>(pxz0, pxz1, U1f, U1b,
                                             nullptr, nullptr, pahi, palo, 0);
    k_init<<<128, 256>>>(0);

    // ----- layer 2 (K = 1024) -----
    {
        const int K = 2 * Hh;
        k_splitW2<<<dim3(G4 / 32, K / 32, 2), tw>>>(W2f, W2b, pwhi, pwlo, K);
        k_hgemm<<<gg, 256>>>(pahi, palo, pwhi, pwlo, b2f, pxz0, K);
        k_hgemm<<<gg, 256>>>(pahi, palo, pwhi + WSTRIDE, pwlo + WSTRIDE, b2b, pxz1, K);
    }
    k_rec<<<2 * NC, REC_THREADS, REC_SMEM>>>(pxz0, pxz1, U2f, U2b, out,
                                             out + (size_t)Bsz * Tt * 1024,
                                             nullptr, nullptr, 1);
}